// round 1
// baseline (speedup 1.0000x reference)
#include <cuda_runtime.h>
#include <math.h>

// ---------------------------------------------------------------------------
// Problem shapes: N=16, F=5, V=4  -> 320 images of 3x224x224
// conv1: 3->3, 3x3, stride2 : 224 -> 111 ; maxpool3/3 -> 37 ; relu
// conv2: 3->1, 3x3, stride2 : 37  -> 18  ; maxpool3/3 -> 6  ; relu
// flatten 36 -> linear -> feat[320,6]
// then tiny graph ops + readout MLP -> out [16,6]
// ---------------------------------------------------------------------------

#define NIMG 320
#define H1_STRIDE (3 * 37 * 37)   // 4107 floats per image after stage 1

__device__ float g_h1[NIMG * H1_STRIDE];   // 5.26 MB scratch (post conv1+pool+relu)
__device__ float g_feat[NIMG * 6];         // per-node features

// ---------------------------------------------------------------------------
// Kernel 1: fused conv1(s2) + maxpool3 + relu.
// One thread per (img, pooled_y, pooled_x). Pool output (py,px) covers conv
// outputs 3py..3py+2 x 3px..3px+2; conv output (cy,cx) reads input rows
// 2cy..2cy+2. So the thread reads a 7x7 input patch per channel starting at
// (6py, 6px). 147 loads, 729 FMAs per thread. HBM-bound.
// ---------------------------------------------------------------------------
__global__ __launch_bounds__(256)
void conv1_pool_kernel(const float* __restrict__ nodes,
                       const float* __restrict__ w,   // [3,3,3,3] OIHW
                       const float* __restrict__ b)   // [3]
{
    __shared__ float sw[81];
    __shared__ float sb[3];
    int tid = threadIdx.x;
    if (tid < 81) sw[tid] = w[tid];
    if (tid < 3)  sb[tid] = b[tid];
    __syncthreads();

    int idx = blockIdx.x * 256 + tid;
    if (idx >= NIMG * 37 * 37) return;
    int px  = idx % 37;
    int rem = idx / 37;
    int py  = rem % 37;
    int img = rem / 37;

    const float* base = nodes + (size_t)img * (3 * 224 * 224)
                              + (size_t)(6 * py) * 224 + 6 * px;

    float acc[9][3];
#pragma unroll
    for (int p = 0; p < 9; p++)
#pragma unroll
        for (int oc = 0; oc < 3; oc++) acc[p][oc] = sb[oc];

#pragma unroll
    for (int ic = 0; ic < 3; ic++) {
        const float* chan = base + ic * 224 * 224;
        float patch[7][7];
#pragma unroll
        for (int r = 0; r < 7; r++)
#pragma unroll
            for (int c = 0; c < 7; c++)
                patch[r][c] = __ldg(chan + r * 224 + c);

#pragma unroll
        for (int ky = 0; ky < 3; ky++)
#pragma unroll
            for (int kx = 0; kx < 3; kx++) {
                float w0 = sw[0 * 27 + ic * 9 + ky * 3 + kx];
                float w1 = sw[1 * 27 + ic * 9 + ky * 3 + kx];
                float w2 = sw[2 * 27 + ic * 9 + ky * 3 + kx];
#pragma unroll
                for (int cy = 0; cy < 3; cy++)
#pragma unroll
                    for (int cx = 0; cx < 3; cx++) {
                        float v = patch[2 * cy + ky][2 * cx + kx];
                        acc[cy * 3 + cx][0] += v * w0;
                        acc[cy * 3 + cx][1] += v * w1;
                        acc[cy * 3 + cx][2] += v * w2;
                    }
            }
    }

#pragma unroll
    for (int oc = 0; oc < 3; oc++) {
        float m = acc[0][oc];
#pragma unroll
        for (int p = 1; p < 9; p++) m = fmaxf(m, acc[p][oc]);
        m = fmaxf(m, 0.0f);  // relu(maxpool(conv))
        g_h1[(size_t)img * H1_STRIDE + oc * 1369 + py * 37 + px] = m;
    }
}

// ---------------------------------------------------------------------------
// Kernel 2: fused conv2(s2) + maxpool3 + relu + 36->6 linear.
// One block per image. Load the 3x37x37 tile into smem (16.4 KB), 36 threads
// each produce one pooled value, then 6 threads do the matvec -> g_feat.
// ---------------------------------------------------------------------------
__global__ __launch_bounds__(128)
void conv2_feat_kernel(const float* __restrict__ c2w,  // [1,3,3,3]
                       const float* __restrict__ c2b,  // [1]
                       const float* __restrict__ lw,   // [36,6]
                       const float* __restrict__ lb)   // [6]
{
    __shared__ float tile[3 * 37 * 37];
    __shared__ float hs[36];
    int img = blockIdx.x;
    const float* src = g_h1 + (size_t)img * H1_STRIDE;
    for (int i = threadIdx.x; i < 3 * 37 * 37; i += 128) tile[i] = src[i];
    __syncthreads();

    int t = threadIdx.x;
    if (t < 36) {
        int py = t / 6, px = t % 6;
        float bias = __ldg(c2b);
        float w[27];
#pragma unroll
        for (int i = 0; i < 27; i++) w[i] = __ldg(c2w + i);
        float m = -1e30f;
#pragma unroll
        for (int dy = 0; dy < 3; dy++)
#pragma unroll
            for (int dx = 0; dx < 3; dx++) {
                int cy = 3 * py + dy, cx = 3 * px + dx;
                float s = bias;
#pragma unroll
                for (int ic = 0; ic < 3; ic++)
#pragma unroll
                    for (int ky = 0; ky < 3; ky++)
#pragma unroll
                        for (int kx = 0; kx < 3; kx++)
                            s += tile[ic * 1369 + (2 * cy + ky) * 37 + (2 * cx + kx)]
                                 * w[ic * 9 + ky * 3 + kx];
                m = fmaxf(m, s);
            }
        hs[t] = fmaxf(m, 0.0f);
    }
    __syncthreads();
    if (t < 6) {
        float s = __ldg(lb + t);
#pragma unroll
        for (int i = 0; i < 36; i++) s += hs[i] * __ldg(lw + i * 6 + t);
        g_feat[img * 6 + t] = s;
    }
}

// ---------------------------------------------------------------------------
// Kernel 3: everything else, one block per sample n (16 blocks, 128 threads).
// Edge weights, attention aggregation, last-frame message, readout MLP.
// Key simplification: wfc_w is [24,1], so
//   link[s][t] = sigmoid(dot(na[s], w[0:12]) + dot(na[t], w[12:24]) + b)
// decomposes into per-node scalars a_src[s] + b_tgt[t].
// ---------------------------------------------------------------------------
__global__ __launch_bounds__(128)
void graph_readout_kernel(const float* __restrict__ pos,     // [16,5,4,6]
                          const float* __restrict__ attmap,  // [16,5,4,4]
                          const float* __restrict__ wfc_w,   // [24,1]
                          const float* __restrict__ wfc_b,   // [1]
                          const float* __restrict__ fm_w,    // [6,6]
                          const float* __restrict__ fm_b,    // [6]
                          const float* __restrict__ lm_w,    // [6,6]
                          const float* __restrict__ lm_b,    // [6]
                          const float* __restrict__ fc1_w,   // [240,120]
                          const float* __restrict__ fc1_b,   // [120]
                          const float* __restrict__ fc2_w,   // [120,60]
                          const float* __restrict__ fc2_b,   // [60]
                          const float* __restrict__ fc3_w,   // [60,6]
                          const float* __restrict__ fc3_b,   // [6]
                          float* __restrict__ out)           // [16,6]
{
    int n = blockIdx.x;
    int t = threadIdx.x;

    __shared__ float feat[20][6];   // fv = f*4 + v
    __shared__ float ps[20][6];
    __shared__ float asrc[20];
    __shared__ float btgt[20];
    __shared__ float pm[20][6];
    __shared__ float inp[240];
    __shared__ float r1[120];
    __shared__ float r2[60];

    if (t < 120) {
        int fv = t / 6, d = t % 6;
        feat[fv][d] = g_feat[(n * 20 + fv) * 6 + d];
        ps[fv][d]   = pos[(n * 20 + fv) * 6 + d];
    }
    __syncthreads();

    if (t < 20) {
        float a = 0.0f, bb = 0.0f;
#pragma unroll
        for (int k = 0; k < 6; k++) {
            a  += feat[t][k] * wfc_w[k]      + ps[t][k] * wfc_w[6 + k];
            bb += feat[t][k] * wfc_w[12 + k] + ps[t][k] * wfc_w[18 + k];
        }
        asrc[t] = a;
        btgt[t] = bb;
    }
    if (t < 120) {
        int fv = t / 6, d = t % 6;
        float s = fm_b[d];
#pragma unroll
        for (int k = 0; k < 6; k++) s += ps[fv][k] * fm_w[k * 6 + d];
        pm[fv][d] = s;
    }
    __syncthreads();

    if (t < 120) {
        int fv = t / 6, d = t % 6;
        int f = fv / 4, tv = fv % 4;   // tv = target node index
        float bias = wfc_b[0];
        float agg = 0.0f;
#pragma unroll
        for (int s = 0; s < 4; s++) {
            float z  = asrc[f * 4 + s] + btgt[f * 4 + tv] + bias;
            float lk = 1.0f / (1.0f + expf(-z));
            float m  = lk + attmap[((n * 5 + f) * 4 + s) * 4 + tv];
            agg += m * pm[f * 4 + s][d];
        }
        if (f > 0) {
            float lm = lm_b[d];
#pragma unroll
            for (int k = 0; k < 6; k++) lm += ps[(f - 1) * 4 + tv][k] * lm_w[k * 6 + d];
            agg += lm;
        }
        // inp = concat(feat, pos_up, axis=-1) flattened to [240]
        inp[fv * 12 + d]     = feat[fv][d];
        inp[fv * 12 + 6 + d] = agg;
    }
    __syncthreads();

    if (t < 120) {
        float s = fc1_b[t];
        for (int i = 0; i < 240; i++) s += inp[i] * fc1_w[i * 120 + t];
        r1[t] = fmaxf(s, 0.0f);
    }
    __syncthreads();
    if (t < 60) {
        float s = fc2_b[t];
        for (int i = 0; i < 120; i++) s += r1[i] * fc2_w[i * 60 + t];
        r2[t] = fmaxf(s, 0.0f);
    }
    __syncthreads();
    if (t < 6) {
        float s = fc3_b[t];
        for (int i = 0; i < 60; i++) s += r2[i] * fc3_w[i * 6 + t];
        out[n * 6 + t] = s;
    }
}

// ---------------------------------------------------------------------------
// Input order (metadata): nodes, pos, attmap, depths,
//   conv1_w, conv1_b, conv2_w, conv2_b, lin_w, lin_b, wfc_w, wfc_b,
//   fm_w, fm_b, lm_w, lm_b, fc1_w, fc1_b, fc2_w, fc2_b, fc3_w, fc3_b
// depths is unused by the reference.
// ---------------------------------------------------------------------------
extern "C" void kernel_launch(void* const* d_in, const int* in_sizes, int n_in,
                              void* d_out, int out_size)
{
    const float* nodes   = (const float*)d_in[0];
    const float* pos     = (const float*)d_in[1];
    const float* attmap  = (const float*)d_in[2];
    const float* conv1_w = (const float*)d_in[4];
    const float* conv1_b = (const float*)d_in[5];
    const float* conv2_w = (const float*)d_in[6];
    const float* conv2_b = (const float*)d_in[7];
    const float* lin_w   = (const float*)d_in[8];
    const float* lin_b   = (const float*)d_in[9];
    const float* wfc_w   = (const float*)d_in[10];
    const float* wfc_b   = (const float*)d_in[11];
    const float* fm_w    = (const float*)d_in[12];
    const float* fm_b    = (const float*)d_in[13];
    const float* lm_w    = (const float*)d_in[14];
    const float* lm_b    = (const float*)d_in[15];
    const float* fc1_w   = (const float*)d_in[16];
    const float* fc1_b   = (const float*)d_in[17];
    const float* fc2_w   = (const float*)d_in[18];
    const float* fc2_b   = (const float*)d_in[19];
    const float* fc3_w   = (const float*)d_in[20];
    const float* fc3_b   = (const float*)d_in[21];
    float* out = (float*)d_out;

    int total1 = NIMG * 37 * 37;
    conv1_pool_kernel<<<(total1 + 255) / 256, 256>>>(nodes, conv1_w, conv1_b);
    conv2_feat_kernel<<<NIMG, 128>>>(conv2_w, conv2_b, lin_w, lin_b);
    graph_readout_kernel<<<16, 128>>>(pos, attmap, wfc_w, wfc_b, fm_w, fm_b,
                                      lm_w, lm_b, fc1_w, fc1_b, fc2_w, fc2_b,
                                      fc3_w, fc3_b, out);
}